// round 4
// baseline (speedup 1.0000x reference)
#include <cuda_runtime.h>

#define NBLK   10
#define NBATCH 2048
#define NCH    64
#define NSKIP  96
#define TILE   16
#define NCOLS  1023
#define CURP   68                      /* padded row stride for cur/del/z */
#define SSP    100                     /* padded row stride for skip/h */
#define NBUF   ((size_t)NBATCH*NCH*NCOLS)   /* 134086656 */
#define NV32   (NBUF/32)                    /* 4190208 thread-tasks */

__device__ float g_currents[NBLK * NBATCH * NCH];

#define FMA4(acc, s, v) do { (acc)[0] += (s)*(v).x; (acc)[1] += (s)*(v).y; \
                             (acc)[2] += (s)*(v).z; (acc)[3] += (s)*(v).w; } while(0)

// ---------------------------------------------------------------------------
// Compute: 128 CTAs x 256 threads. CTA owns 16 samples.
// Thread = (sp 0..15, tg 0..15): 1 sample x 4 channels.
// ---------------------------------------------------------------------------
__global__ __launch_bounds__(256, 1) void wn_compute(
    const float* __restrict__ x,   const float* __restrict__ buf,
    const float* __restrict__ inp_w, const float* __restrict__ inp_b,
    const float* __restrict__ fw0, const float* __restrict__ fw1, const float* __restrict__ fb,
    const float* __restrict__ gw0, const float* __restrict__ gw1, const float* __restrict__ gb,
    const float* __restrict__ rw,  const float* __restrict__ rb,
    const float* __restrict__ sw,  const float* __restrict__ sb,
    const float* __restrict__ h1w, const float* __restrict__ h1b,
    const float* __restrict__ h2w, const float* __restrict__ h2b,
    float* __restrict__ out)
{
    extern __shared__ float sm[];
    float* cur = sm;                          // 16*68
    float* zs  = cur + TILE*CURP;             // 16*68 (x tile, then z)
    float* del = zs  + TILE*CURP;             // 10*16*68 delayed taps
    float* w0  = del + NBLK*TILE*CURP;        // 4096 transposed [k][t]
    float* w1  = w0 + 4096;
    float* w2  = w1 + 4096;
    float* w3  = w2 + 4096;
    float* wrs = w3 + 4096;
    float* wst = wrs + 4096;                  // 64*96 skip weights transposed
    float* bia = wst + 6144;                  // fb[64] gb[64] rb[64] sb[96]
    float* ssm = bia + 288;                   // 16*100
    float* hsm = ssm + TILE*SSP;              // 16*100

    const int tid   = threadIdx.x;
    const int bbase = blockIdx.x * TILE;
    const int sp = tid >> 4, tg = tid & 15;
    const int t0 = tg * 4, ts = tg * 6;

    // ---- x tile (16 x 32) into zs scratch ----
    for (int idx = tid; idx < TILE*32; idx += 256)
        zs[idx] = x[(bbase + (idx >> 5))*32 + (idx & 31)];

    // ---- preload all delayed taps: del[i][s][c] = buf[b,c,2^i-1] ----
    for (int idx = tid; idx < NBLK*TILE*NCH; idx += 256) {
        int i = idx >> 10, r = idx & 1023;
        int s = r >> 6, c = r & 63;
        int off = (1 << i) - 1;
        del[(i*TILE + s)*CURP + c] =
            buf[((size_t)(bbase + s)*NCH + c)*NCOLS + off];
    }
    __syncthreads();

    // ---- input projection: cur = x @ inp_w.T + inp_b ----
    {
        float a[4];
        #pragma unroll
        for (int j = 0; j < 4; ++j) a[j] = inp_b[t0 + j];
        #pragma unroll 8
        for (int k = 0; k < 32; ++k) {
            float xk = zs[sp*32 + k];
            #pragma unroll
            for (int j = 0; j < 4; ++j)
                a[j] += xk * inp_w[(t0 + j)*32 + k];
        }
        #pragma unroll
        for (int j = 0; j < 4; ++j) cur[sp*CURP + t0 + j] = a[j];
    }

    float ssum[6];
    #pragma unroll
    for (int j = 0; j < 6; ++j) ssum[j] = 0.f;

    for (int i = 0; i < NBLK; ++i) {
        __syncthreads();   // prev iter done with weights; cur updates visible

        // ---- stage transposed weights for this block ----
        {
            const float* srcs[5] = { fw0 + i*4096, fw1 + i*4096, gw0 + i*4096,
                                     gw1 + i*4096, rw + i*4096 };
            float* dsts[5] = { w0, w1, w2, w3, wrs };
            #pragma unroll
            for (int mm = 0; mm < 5; ++mm) {
                const float* s = srcs[mm]; float* d = dsts[mm];
                #pragma unroll
                for (int it = 0; it < 4; ++it) {
                    int idx = it*256 + tid;           // 1024 float4 total
                    int q = idx >> 6, t = idx & 63;
                    float4 v = *(const float4*)(s + t*64 + q*4);
                    d[(4*q+0)*64+t] = v.x; d[(4*q+1)*64+t] = v.y;
                    d[(4*q+2)*64+t] = v.z; d[(4*q+3)*64+t] = v.w;
                }
            }
            const float* s = sw + i*NSKIP*NCH;        // [96][64] -> wst[64][96]
            #pragma unroll
            for (int it = 0; it < 6; ++it) {
                int idx = it*256 + tid;               // 1536 float4 total
                int q = idx / 96, t = idx - q*96;
                float4 v = *(const float4*)(s + t*64 + q*4);
                wst[(4*q+0)*96+t] = v.x; wst[(4*q+1)*96+t] = v.y;
                wst[(4*q+2)*96+t] = v.z; wst[(4*q+3)*96+t] = v.w;
            }
            if (tid < 64) {
                bia[tid]     = fb[i*64 + tid];
                bia[64+tid]  = gb[i*64 + tid];
                bia[128+tid] = rb[i*64 + tid];
            }
            if (tid >= 64 && tid < 160) bia[192 + tid - 64] = sb[i*NSKIP + tid - 64];
        }
        __syncthreads();

        // ---- f/g GEMMs ----
        float f[4], g[4];
        #pragma unroll
        for (int j = 0; j < 4; ++j) { f[j] = bia[t0+j]; g[j] = bia[64+t0+j]; }
        const float* dle = del + i*TILE*CURP + sp*CURP;
        const float* cu  = cur + sp*CURP;
        #pragma unroll 8
        for (int k = 0; k < 64; ++k) {
            float dk = dle[k], ck = cu[k];
            float4 wa = *(const float4*)(w0 + k*64 + t0);
            float4 wb = *(const float4*)(w1 + k*64 + t0);
            float4 wc = *(const float4*)(w2 + k*64 + t0);
            float4 wd = *(const float4*)(w3 + k*64 + t0);
            FMA4(f, dk, wa); FMA4(f, ck, wb);
            FMA4(g, dk, wc); FMA4(g, ck, wd);
        }

        // ---- z = tanh(f)*sigmoid(g) ----
        float z[4];
        #pragma unroll
        for (int j = 0; j < 4; ++j)
            z[j] = tanhf(f[j]) * (1.f / (1.f + __expf(-g[j])));
        *(float4*)(zs + sp*CURP + t0) = make_float4(z[0], z[1], z[2], z[3]);
        __syncthreads();   // f/g reads of del[i]/cur done; z visible

        // ---- snapshot pre-update current (own slot) to global scratch ----
        {
            float4 c4 = *(const float4*)(cur + sp*CURP + t0);
            *(float4*)(g_currents + ((size_t)i*NBATCH + bbase + sp)*NCH + t0) = c4;
        }

        // ---- res + skip GEMMs ----
        float r[4];
        #pragma unroll
        for (int j = 0; j < 4; ++j) r[j] = bia[128 + t0 + j];
        const float* zrow = zs + sp*CURP;
        #pragma unroll 8
        for (int k = 0; k < 64; ++k) {
            float zk = zrow[k];
            float4 wv = *(const float4*)(wrs + k*64 + t0);
            FMA4(r, zk, wv);
            const float* wsk = wst + k*96 + ts;
            #pragma unroll
            for (int j = 0; j < 6; ++j) ssum[j] += zk * wsk[j];
        }
        #pragma unroll
        for (int j = 0; j < 6; ++j) ssum[j] += bia[192 + ts + j];

        // ---- residual update (owner-exclusive) ----
        {
            float4 c4 = *(float4*)(cur + sp*CURP + t0);
            c4.x += 0.3f*r[0]; c4.y += 0.3f*r[1];
            c4.z += 0.3f*r[2]; c4.w += 0.3f*r[3];
            *(float4*)(cur + sp*CURP + t0) = c4;
        }
    }

    // ---- head ----
    __syncthreads();
    #pragma unroll
    for (int j = 0; j < 6; ++j)
        ssm[sp*SSP + ts + j] = fmaxf(ssum[j], 0.f);
    for (int idx = tid; idx < NSKIP*NSKIP; idx += 256) {   // h1w transposed
        int k = idx / 96, t = idx - k*96;
        w0[idx] = h1w[t*96 + k];
    }
    __syncthreads();
    {
        float a[6];
        #pragma unroll
        for (int j = 0; j < 6; ++j) a[j] = h1b[ts + j];
        #pragma unroll 4
        for (int k = 0; k < 96; ++k) {
            float u = ssm[sp*SSP + k];
            const float* wk = w0 + k*96 + ts;
            #pragma unroll
            for (int j = 0; j < 6; ++j) a[j] += u * wk[j];
        }
        #pragma unroll
        for (int j = 0; j < 6; ++j)
            hsm[sp*SSP + ts + j] = fmaxf(a[j], 0.f);
    }
    __syncthreads();
    if (tid < 32) {
        int s = tid >> 1, jj = tid & 1;
        float a = h2b[jj];
        #pragma unroll 4
        for (int k = 0; k < 96; ++k)
            a += hsm[s*SSP + k] * h2w[jj*96 + k];
        out[(bbase + s)*2 + jj] = a;
    }
}

// ---------------------------------------------------------------------------
// Shift: dst[n] = src[n+1]. Single pass, 32 floats/thread, coalesced LDG.128
// (lane-interleaved), boundary value loaded CONCURRENTLY with vector loads.
// grid 16368 x 256 covers NV32 = 4190208 tasks exactly.
// ---------------------------------------------------------------------------
__global__ __launch_bounds__(256) void wn_shift(const float* __restrict__ src,
                                                float* __restrict__ dst)
{
    const size_t m = (size_t)blockIdx.x*256 + threadIdx.x;   // < NV32 exact
    const unsigned lane = threadIdx.x & 31;

    float lastv = 0.f;
    if (lane == 31) {
        size_t g = m*32 + 32;
        lastv = src[g < NBUF ? g : NBUF - 1];   // clamp slot is insertion col
    }
    const float4* s4 = (const float4*)src + m*8;
    float4 A0 = s4[0], A1 = s4[1], A2 = s4[2], A3 = s4[3];
    float4 A4 = s4[4], A5 = s4[5], A6 = s4[6], A7 = s4[7];
    float nxt = __shfl_down_sync(0xffffffffu, A0.x, 1);
    if (lane == 31) nxt = lastv;
    float4* d4 = (float4*)dst + m*8;
    d4[0] = make_float4(A0.y, A0.z, A0.w, A1.x);
    d4[1] = make_float4(A1.y, A1.z, A1.w, A2.x);
    d4[2] = make_float4(A2.y, A2.z, A2.w, A3.x);
    d4[3] = make_float4(A3.y, A3.z, A3.w, A4.x);
    d4[4] = make_float4(A4.y, A4.z, A4.w, A5.x);
    d4[5] = make_float4(A5.y, A5.z, A5.w, A6.x);
    d4[6] = make_float4(A6.y, A6.z, A6.w, A7.x);
    d4[7] = make_float4(A7.y, A7.z, A7.w, nxt);
}

// ---------------------------------------------------------------------------
// Scatter: overwrite the 10 insertion columns j = 2^(i+1)-2 with current_i.
// ---------------------------------------------------------------------------
__global__ __launch_bounds__(256) void wn_scatter(float* __restrict__ dst)
{
    int idx = blockIdx.x*blockDim.x + threadIdx.x;
    if (idx < NBLK*NBATCH*NCH) {
        int i = idx >> 17;                 // / (2048*64)
        int r = idx & ((1 << 17) - 1);     // b*64+c
        int j = (2 << i) - 2;              // 2^(i+1)-2
        dst[(size_t)r*NCOLS + j] = g_currents[idx];
    }
}

extern "C" void kernel_launch(void* const* d_in, const int* in_sizes, int n_in,
                              void* d_out, int out_size)
{
    const float* x     = (const float*)d_in[0];
    const float* buf   = (const float*)d_in[1];
    const float* inp_w = (const float*)d_in[2];
    const float* inp_b = (const float*)d_in[3];
    const float* fw0   = (const float*)d_in[4];
    const float* fw1   = (const float*)d_in[5];
    const float* fb    = (const float*)d_in[6];
    const float* gw0   = (const float*)d_in[7];
    const float* gw1   = (const float*)d_in[8];
    const float* gb    = (const float*)d_in[9];
    const float* rw    = (const float*)d_in[10];
    const float* rb    = (const float*)d_in[11];
    const float* sw    = (const float*)d_in[12];
    const float* sb    = (const float*)d_in[13];
    const float* h1w   = (const float*)d_in[14];
    const float* h1b   = (const float*)d_in[15];
    const float* h2w   = (const float*)d_in[16];
    const float* h2b   = (const float*)d_in[17];

    float* out  = (float*)d_out;            // (2048, 2)
    float* nbuf = out + NBATCH*2;           // (2048, 64, 1023)

    const int smem_bytes =
        (TILE*CURP*2 + NBLK*TILE*CURP + 5*4096 + 6144 + 288 + 2*TILE*SSP)
        * (int)sizeof(float);               // 172672 B
    cudaFuncSetAttribute(wn_compute, cudaFuncAttributeMaxDynamicSharedMemorySize,
                         smem_bytes);

    wn_compute<<<NBATCH/TILE, 256, smem_bytes>>>(
        x, buf, inp_w, inp_b, fw0, fw1, fb, gw0, gw1, gb,
        rw, rb, sw, sb, h1w, h1b, h2w, h2b, out);

    wn_shift<<<(int)(NV32/256), 256>>>(buf, nbuf);

    wn_scatter<<<(NBLK*NBATCH*NCH)/256, 256>>>(nbuf);
}

// round 5
// speedup vs baseline: 2.1380x; 2.1380x over previous
#include <cuda_runtime.h>

#define NBLK   10
#define NBATCH 2048
#define NCH    64
#define NSKIP  96
#define TILE   16
#define NCOLS  1023
#define CURP   68                      /* padded row stride for cur/del/z */
#define SSP    100                     /* padded row stride for skip/h */
#define NBUF   ((size_t)NBATCH*NCH*NCOLS)   /* 134086656 */

__device__ float g_currents[NBLK * NBATCH * NCH];

#define FMA4(acc, s, v) do { (acc)[0] += (s)*(v).x; (acc)[1] += (s)*(v).y; \
                             (acc)[2] += (s)*(v).z; (acc)[3] += (s)*(v).w; } while(0)

// ---------------------------------------------------------------------------
// Compute kernel: 128 CTAs x 128 threads (R1-proven layout).
// Thread = (sp 0..7, tg 0..15): 2 samples x 4 channels register tile.
// ---------------------------------------------------------------------------
__global__ __launch_bounds__(128, 1) void wn_compute(
    const float* __restrict__ x,   const float* __restrict__ buf,
    const float* __restrict__ inp_w, const float* __restrict__ inp_b,
    const float* __restrict__ fw0, const float* __restrict__ fw1, const float* __restrict__ fb,
    const float* __restrict__ gw0, const float* __restrict__ gw1, const float* __restrict__ gb,
    const float* __restrict__ rw,  const float* __restrict__ rb,
    const float* __restrict__ sw,  const float* __restrict__ sb,
    const float* __restrict__ h1w, const float* __restrict__ h1b,
    const float* __restrict__ h2w, const float* __restrict__ h2b,
    float* __restrict__ out)
{
    extern __shared__ float sm[];
    float* cur = sm;                          // 16*68
    float* del = cur + TILE*CURP;             // 10*16*68
    float* zs  = del + NBLK*TILE*CURP;        // 16*68
    float* w0  = zs  + TILE*CURP;             // 4096  (transposed [k][t], row 64)
    float* w1  = w0 + 4096;
    float* w2  = w1 + 4096;
    float* w3  = w2 + 4096;
    float* wrs = w3 + 4096;                   // res weights
    float* wst = wrs + 4096;                  // 64*96 skip weights transposed
    float* bia = wst + 6144;                  // fb[64] gb[64] rb[64] sb[96]
    float* ssm = bia + 288;                   // 16*100 skip sums
    float* hsm = ssm + TILE*SSP;              // 16*100 hidden

    const int tid  = threadIdx.x;
    const int lane = tid & 31, warp = tid >> 5;
    const int sp = tid >> 4, tg = tid & 15;
    const int s0 = sp*2, s1 = s0+1, t0 = tg*4;
    const int bbase = blockIdx.x * TILE;

    // ---- x tile into zs scratch (16 x 32) ----
    for (int idx = tid; idx < TILE*32; idx += 128) {
        int s = idx >> 5, k = idx & 31;
        zs[idx] = x[(bbase+s)*32 + k];
    }
    __syncthreads();

    // ---- input projection: cur = x @ inp_w.T + inp_b ----
    {
        float a0[4], a1[4];
        #pragma unroll
        for (int j = 0; j < 4; ++j) { a0[j] = inp_b[t0+j]; a1[j] = a0[j]; }
        #pragma unroll 8
        for (int k = 0; k < 32; ++k) {
            float x0 = zs[s0*32+k], x1 = zs[s1*32+k];
            #pragma unroll
            for (int j = 0; j < 4; ++j) {
                float w = inp_w[(t0+j)*32 + k];
                a0[j] += x0*w; a1[j] += x1*w;
            }
        }
        #pragma unroll
        for (int j = 0; j < 4; ++j) {
            cur[s0*CURP + t0 + j] = a0[j];
            cur[s1*CURP + t0 + j] = a1[j];
        }
    }

    // ---- preload all delayed taps: del[i][s][c] = buf[b, c, 2^i - 1] ----
    for (int idx = tid; idx < NBLK*TILE*NCH; idx += 128) {
        int i = idx >> 10;
        int r = idx & 1023;
        int s = r >> 6, c = r & 63;
        int off = (1 << i) - 1;
        del[(i*TILE + s)*CURP + c] =
            buf[((size_t)(bbase+s)*NCH + c)*NCOLS + off];
    }

    float ssum0[6], ssum1[6];
    #pragma unroll
    for (int j = 0; j < 6; ++j) { ssum0[j] = 0.f; ssum1[j] = 0.f; }
    const int ts = tg*6;

    for (int i = 0; i < NBLK; ++i) {
        __syncthreads();

        // snapshot current entering block i -> g_currents[i]
        {
            float4* dst = (float4*)(g_currents + (size_t)i*NBATCH*NCH + (size_t)bbase*NCH);
            for (int idx = tid; idx < TILE*NCH/4; idx += 128) {
                int s = idx >> 4, q = idx & 15;
                dst[idx] = *(const float4*)(cur + s*CURP + q*4);
            }
        }

        // ---- stage transposed weights for this block ----
        {
            const float* srcs[5] = { fw0 + i*4096, fw1 + i*4096, gw0 + i*4096,
                                     gw1 + i*4096, rw + i*4096 };
            float* dsts[5] = { w0, w1, w2, w3, wrs };
            #pragma unroll
            for (int mm = 0; mm < 5; ++mm) {
                const float* s = srcs[mm]; float* d = dsts[mm];
                #pragma unroll
                for (int th = 0; th < 2; ++th) {
                    int t = th*32 + lane;
                    #pragma unroll
                    for (int kc = 0; kc < 4; ++kc) {
                        int k0 = warp*16 + kc*4;
                        float4 v = *(const float4*)(s + t*64 + k0);
                        d[(k0+0)*64+t] = v.x; d[(k0+1)*64+t] = v.y;
                        d[(k0+2)*64+t] = v.z; d[(k0+3)*64+t] = v.w;
                    }
                }
            }
            const float* s = sw + i*NSKIP*NCH;   // [96][64] -> wst[64][96]
            #pragma unroll
            for (int th = 0; th < 3; ++th) {
                int t = th*32 + lane;
                #pragma unroll
                for (int kc = 0; kc < 4; ++kc) {
                    int k0 = warp*16 + kc*4;
                    float4 v = *(const float4*)(s + t*64 + k0);
                    wst[(k0+0)*96+t] = v.x; wst[(k0+1)*96+t] = v.y;
                    wst[(k0+2)*96+t] = v.z; wst[(k0+3)*96+t] = v.w;
                }
            }
            if (tid < 64) {
                bia[tid]      = fb[i*64+tid];
                bia[64+tid]   = gb[i*64+tid];
                bia[128+tid]  = rb[i*64+tid];
            }
            if (tid < 96) bia[192+tid] = sb[i*NSKIP+tid];
        }
        __syncthreads();

        // ---- f/g GEMMs ----
        float f0[4], f1[4], g0[4], g1[4];
        #pragma unroll
        for (int j = 0; j < 4; ++j) {
            f0[j] = bia[t0+j];    f1[j] = f0[j];
            g0[j] = bia[64+t0+j]; g1[j] = g0[j];
        }
        const float* dle = del + i*TILE*CURP;
        #pragma unroll 8
        for (int k = 0; k < 64; ++k) {
            float d0 = dle[s0*CURP+k], d1 = dle[s1*CURP+k];
            float c0 = cur[s0*CURP+k], c1 = cur[s1*CURP+k];
            float4 wa = *(const float4*)(w0 + k*64 + t0);
            float4 wb = *(const float4*)(w1 + k*64 + t0);
            float4 wc = *(const float4*)(w2 + k*64 + t0);
            float4 wd = *(const float4*)(w3 + k*64 + t0);
            FMA4(f0, d0, wa); FMA4(f0, c0, wb);
            FMA4(f1, d1, wa); FMA4(f1, c1, wb);
            FMA4(g0, d0, wc); FMA4(g0, c0, wd);
            FMA4(g1, d1, wc); FMA4(g1, c1, wd);
        }

        // ---- z = tanh(f) * sigmoid(g) ----
        float z0[4], z1[4];
        #pragma unroll
        for (int j = 0; j < 4; ++j) {
            z0[j] = tanhf(f0[j]) * (1.f / (1.f + __expf(-g0[j])));
            z1[j] = tanhf(f1[j]) * (1.f / (1.f + __expf(-g1[j])));
        }
        *(float4*)(zs + s0*CURP + t0) = make_float4(z0[0],z0[1],z0[2],z0[3]);
        *(float4*)(zs + s1*CURP + t0) = make_float4(z1[0],z1[1],z1[2],z1[3]);
        __syncthreads();

        // ---- res + skip GEMMs ----
        float r0[4], r1[4];
        #pragma unroll
        for (int j = 0; j < 4; ++j) { r0[j] = bia[128+t0+j]; r1[j] = r0[j]; }
        #pragma unroll 8
        for (int k = 0; k < 64; ++k) {
            float zk0 = zs[s0*CURP+k], zk1 = zs[s1*CURP+k];
            float4 wv = *(const float4*)(wrs + k*64 + t0);
            FMA4(r0, zk0, wv); FMA4(r1, zk1, wv);
            const float* wsk = wst + k*96 + ts;
            #pragma unroll
            for (int j = 0; j < 6; ++j) {
                float w = wsk[j];
                ssum0[j] += zk0*w; ssum1[j] += zk1*w;
            }
        }
        #pragma unroll
        for (int j = 0; j < 6; ++j) {
            ssum0[j] += bia[192+ts+j];
            ssum1[j] += bia[192+ts+j];
        }

        // ---- residual update of current (owner-exclusive) ----
        {
            float4 c4 = *(float4*)(cur + s0*CURP + t0);
            c4.x += 0.3f*r0[0]; c4.y += 0.3f*r0[1];
            c4.z += 0.3f*r0[2]; c4.w += 0.3f*r0[3];
            *(float4*)(cur + s0*CURP + t0) = c4;
            float4 d4 = *(float4*)(cur + s1*CURP + t0);
            d4.x += 0.3f*r1[0]; d4.y += 0.3f*r1[1];
            d4.z += 0.3f*r1[2]; d4.w += 0.3f*r1[3];
            *(float4*)(cur + s1*CURP + t0) = d4;
        }
    }

    // ---- head ----
    __syncthreads();
    #pragma unroll
    for (int j = 0; j < 6; ++j) {
        ssm[s0*SSP + ts + j] = fmaxf(ssum0[j], 0.f);
        ssm[s1*SSP + ts + j] = fmaxf(ssum1[j], 0.f);
    }
    float* h1T = w0;
    for (int idx = tid; idx < NSKIP*NSKIP; idx += 128) {
        int k = idx / 96, t = idx - k*96;
        h1T[idx] = h1w[t*96 + k];
    }
    __syncthreads();
    {
        float a0[6], a1[6];
        #pragma unroll
        for (int j = 0; j < 6; ++j) { a0[j] = h1b[ts+j]; a1[j] = a0[j]; }
        #pragma unroll 4
        for (int k = 0; k < 96; ++k) {
            float u0 = ssm[s0*SSP+k], u1 = ssm[s1*SSP+k];
            const float* wk = h1T + k*96 + ts;
            #pragma unroll
            for (int j = 0; j < 6; ++j) {
                float w = wk[j];
                a0[j] += u0*w; a1[j] += u1*w;
            }
        }
        #pragma unroll
        for (int j = 0; j < 6; ++j) {
            hsm[s0*SSP + ts + j] = fmaxf(a0[j], 0.f);
            hsm[s1*SSP + ts + j] = fmaxf(a1[j], 0.f);
        }
    }
    __syncthreads();
    if (tid < 32) {
        int s = tid >> 1, jj = tid & 1;
        float a = h2b[jj];
        #pragma unroll 4
        for (int k = 0; k < 96; ++k)
            a += hsm[s*SSP+k] * h2w[jj*96+k];
        out[(bbase+s)*2 + jj] = a;
    }
}

// ---------------------------------------------------------------------------
// Shift: dst[n] = src[n+1], FULLY COALESCED (lane-interleaved float4).
// Warp owns 2048 contiguous floats: A[r] = f4[r*32 + lane], r = 0..15.
// Realignment in registers via shuffles; one hoisted boundary scalar/warp.
// Grid 8184 x 256 covers NBUF exactly (8184*16384 = 134086656).
// ---------------------------------------------------------------------------
__global__ __launch_bounds__(256) void wn_shift(const float* __restrict__ src,
                                                float* __restrict__ dst)
{
    const int warp = threadIdx.x >> 5;
    const unsigned lane = threadIdx.x & 31;
    const size_t base = (size_t)blockIdx.x*16384 + (size_t)warp*2048;  // floats
    const float4* s4 = (const float4*)(src + base);
    float4*       d4 = (float4*)(dst + base);

    // boundary value issued concurrently with the vector loads
    float bnd = 0.f;
    if (lane == 31) {
        size_t g = base + 2048;
        bnd = src[g < NBUF ? g : NBUF - 1];   // clamp slot is an insertion col
    }
    float4 A[16];
    #pragma unroll
    for (int r = 0; r < 16; ++r) A[r] = s4[r*32 + lane];

    #pragma unroll
    for (int r = 0; r < 16; ++r) {
        float nd = __shfl_down_sync(0xffffffffu, A[r].x, 1);
        float n0 = (r < 15) ? __shfl_sync(0xffffffffu, A[r+1].x, 0) : bnd;
        float nxt = (lane == 31) ? n0 : nd;
        d4[r*32 + lane] = make_float4(A[r].y, A[r].z, A[r].w, nxt);
    }
}

// ---------------------------------------------------------------------------
// Scatter: overwrite the 10 insertion columns j = 2^(i+1)-2 with current_i.
// ---------------------------------------------------------------------------
__global__ __launch_bounds__(256) void wn_scatter(float* __restrict__ dst)
{
    int idx = blockIdx.x*blockDim.x + threadIdx.x;
    if (idx < NBLK*NBATCH*NCH) {
        int i = idx >> 17;                 // / (2048*64)
        int r = idx & ((1 << 17) - 1);     // b*64+c
        int j = (2 << i) - 2;              // 2^(i+1)-2
        dst[(size_t)r*NCOLS + j] = g_currents[idx];
    }
}

extern "C" void kernel_launch(void* const* d_in, const int* in_sizes, int n_in,
                              void* d_out, int out_size)
{
    const float* x     = (const float*)d_in[0];
    const float* buf   = (const float*)d_in[1];
    const float* inp_w = (const float*)d_in[2];
    const float* inp_b = (const float*)d_in[3];
    const float* fw0   = (const float*)d_in[4];
    const float* fw1   = (const float*)d_in[5];
    const float* fb    = (const float*)d_in[6];
    const float* gw0   = (const float*)d_in[7];
    const float* gw1   = (const float*)d_in[8];
    const float* gb    = (const float*)d_in[9];
    const float* rw    = (const float*)d_in[10];
    const float* rb    = (const float*)d_in[11];
    const float* sw    = (const float*)d_in[12];
    const float* sb    = (const float*)d_in[13];
    const float* h1w   = (const float*)d_in[14];
    const float* h1b   = (const float*)d_in[15];
    const float* h2w   = (const float*)d_in[16];
    const float* h2b   = (const float*)d_in[17];

    float* out  = (float*)d_out;            // (2048, 2)
    float* nbuf = out + NBATCH*2;           // (2048, 64, 1023)

    const int smem_bytes = (TILE*CURP*(NBLK+2) + 5*4096 + 6144 + 288 + 2*TILE*SSP)
                           * (int)sizeof(float);
    cudaFuncSetAttribute(wn_compute, cudaFuncAttributeMaxDynamicSharedMemorySize,
                         smem_bytes);

    wn_compute<<<NBATCH/TILE, 128, smem_bytes>>>(
        x, buf, inp_w, inp_b, fw0, fw1, fb, gw0, gw1, gb,
        rw, rb, sw, sb, h1w, h1b, h2w, h2b, out);

    wn_shift<<<8184, 256>>>(buf, nbuf);

    wn_scatter<<<(NBLK*NBATCH*NCH)/256, 256>>>(nbuf);
}

// round 6
// speedup vs baseline: 2.1773x; 1.0184x over previous
#include <cuda_runtime.h>

#define NBLK   10
#define NBATCH 2048
#define NCH    64
#define NSKIP  96
#define TILE   16
#define NCOLS  1023
#define CURP   68                      /* padded row stride for cur/del/z */
#define SSP    100                     /* padded row stride for skip/h */
#define NBUF   ((size_t)NBATCH*NCH*NCOLS)   /* 134086656 */

__device__ float g_currents[NBLK * NBATCH * NCH];

#define FMA4(acc, s, v) do { (acc)[0] += (s)*(v).x; (acc)[1] += (s)*(v).y; \
                             (acc)[2] += (s)*(v).z; (acc)[3] += (s)*(v).w; } while(0)

// ---------------------------------------------------------------------------
// Compute kernel: 128 CTAs x 128 threads (proven 140us layout, unchanged).
// Thread = (sp 0..7, tg 0..15): 2 samples x 4 channels register tile.
// ---------------------------------------------------------------------------
__global__ __launch_bounds__(128, 1) void wn_compute(
    const float* __restrict__ x,   const float* __restrict__ buf,
    const float* __restrict__ inp_w, const float* __restrict__ inp_b,
    const float* __restrict__ fw0, const float* __restrict__ fw1, const float* __restrict__ fb,
    const float* __restrict__ gw0, const float* __restrict__ gw1, const float* __restrict__ gb,
    const float* __restrict__ rw,  const float* __restrict__ rb,
    const float* __restrict__ sw,  const float* __restrict__ sb,
    const float* __restrict__ h1w, const float* __restrict__ h1b,
    const float* __restrict__ h2w, const float* __restrict__ h2b,
    float* __restrict__ out)
{
    extern __shared__ float sm[];
    float* cur = sm;                          // 16*68
    float* del = cur + TILE*CURP;             // 10*16*68
    float* zs  = del + NBLK*TILE*CURP;        // 16*68
    float* w0  = zs  + TILE*CURP;             // 4096  (transposed [k][t], row 64)
    float* w1  = w0 + 4096;
    float* w2  = w1 + 4096;
    float* w3  = w2 + 4096;
    float* wrs = w3 + 4096;                   // res weights
    float* wst = wrs + 4096;                  // 64*96 skip weights transposed
    float* bia = wst + 6144;                  // fb[64] gb[64] rb[64] sb[96]
    float* ssm = bia + 288;                   // 16*100 skip sums
    float* hsm = ssm + TILE*SSP;              // 16*100 hidden

    const int tid  = threadIdx.x;
    const int lane = tid & 31, warp = tid >> 5;
    const int sp = tid >> 4, tg = tid & 15;
    const int s0 = sp*2, s1 = s0+1, t0 = tg*4;
    const int bbase = blockIdx.x * TILE;

    // ---- x tile into zs scratch (16 x 32) ----
    for (int idx = tid; idx < TILE*32; idx += 128) {
        int s = idx >> 5, k = idx & 31;
        zs[idx] = x[(bbase+s)*32 + k];
    }
    __syncthreads();

    // ---- input projection: cur = x @ inp_w.T + inp_b ----
    {
        float a0[4], a1[4];
        #pragma unroll
        for (int j = 0; j < 4; ++j) { a0[j] = inp_b[t0+j]; a1[j] = a0[j]; }
        #pragma unroll 8
        for (int k = 0; k < 32; ++k) {
            float x0 = zs[s0*32+k], x1 = zs[s1*32+k];
            #pragma unroll
            for (int j = 0; j < 4; ++j) {
                float w = inp_w[(t0+j)*32 + k];
                a0[j] += x0*w; a1[j] += x1*w;
            }
        }
        #pragma unroll
        for (int j = 0; j < 4; ++j) {
            cur[s0*CURP + t0 + j] = a0[j];
            cur[s1*CURP + t0 + j] = a1[j];
        }
    }

    // ---- preload all delayed taps: del[i][s][c] = buf[b, c, 2^i - 1] ----
    for (int idx = tid; idx < NBLK*TILE*NCH; idx += 128) {
        int i = idx >> 10;
        int r = idx & 1023;
        int s = r >> 6, c = r & 63;
        int off = (1 << i) - 1;
        del[(i*TILE + s)*CURP + c] =
            buf[((size_t)(bbase+s)*NCH + c)*NCOLS + off];
    }

    float ssum0[6], ssum1[6];
    #pragma unroll
    for (int j = 0; j < 6; ++j) { ssum0[j] = 0.f; ssum1[j] = 0.f; }
    const int ts = tg*6;

    for (int i = 0; i < NBLK; ++i) {
        __syncthreads();

        // snapshot current entering block i -> g_currents[i]
        {
            float4* dst = (float4*)(g_currents + (size_t)i*NBATCH*NCH + (size_t)bbase*NCH);
            for (int idx = tid; idx < TILE*NCH/4; idx += 128) {
                int s = idx >> 4, q = idx & 15;
                dst[idx] = *(const float4*)(cur + s*CURP + q*4);
            }
        }

        // ---- stage transposed weights for this block ----
        {
            const float* srcs[5] = { fw0 + i*4096, fw1 + i*4096, gw0 + i*4096,
                                     gw1 + i*4096, rw + i*4096 };
            float* dsts[5] = { w0, w1, w2, w3, wrs };
            #pragma unroll
            for (int mm = 0; mm < 5; ++mm) {
                const float* s = srcs[mm]; float* d = dsts[mm];
                #pragma unroll
                for (int th = 0; th < 2; ++th) {
                    int t = th*32 + lane;
                    #pragma unroll
                    for (int kc = 0; kc < 4; ++kc) {
                        int k0 = warp*16 + kc*4;
                        float4 v = *(const float4*)(s + t*64 + k0);
                        d[(k0+0)*64+t] = v.x; d[(k0+1)*64+t] = v.y;
                        d[(k0+2)*64+t] = v.z; d[(k0+3)*64+t] = v.w;
                    }
                }
            }
            const float* s = sw + i*NSKIP*NCH;   // [96][64] -> wst[64][96]
            #pragma unroll
            for (int th = 0; th < 3; ++th) {
                int t = th*32 + lane;
                #pragma unroll
                for (int kc = 0; kc < 4; ++kc) {
                    int k0 = warp*16 + kc*4;
                    float4 v = *(const float4*)(s + t*64 + k0);
                    wst[(k0+0)*96+t] = v.x; wst[(k0+1)*96+t] = v.y;
                    wst[(k0+2)*96+t] = v.z; wst[(k0+3)*96+t] = v.w;
                }
            }
            if (tid < 64) {
                bia[tid]      = fb[i*64+tid];
                bia[64+tid]   = gb[i*64+tid];
                bia[128+tid]  = rb[i*64+tid];
            }
            if (tid < 96) bia[192+tid] = sb[i*NSKIP+tid];
        }
        __syncthreads();

        // ---- f/g GEMMs ----
        float f0[4], f1[4], g0[4], g1[4];
        #pragma unroll
        for (int j = 0; j < 4; ++j) {
            f0[j] = bia[t0+j];    f1[j] = f0[j];
            g0[j] = bia[64+t0+j]; g1[j] = g0[j];
        }
        const float* dle = del + i*TILE*CURP;
        #pragma unroll 8
        for (int k = 0; k < 64; ++k) {
            float d0 = dle[s0*CURP+k], d1 = dle[s1*CURP+k];
            float c0 = cur[s0*CURP+k], c1 = cur[s1*CURP+k];
            float4 wa = *(const float4*)(w0 + k*64 + t0);
            float4 wb = *(const float4*)(w1 + k*64 + t0);
            float4 wc = *(const float4*)(w2 + k*64 + t0);
            float4 wd = *(const float4*)(w3 + k*64 + t0);
            FMA4(f0, d0, wa); FMA4(f0, c0, wb);
            FMA4(f1, d1, wa); FMA4(f1, c1, wb);
            FMA4(g0, d0, wc); FMA4(g0, c0, wd);
            FMA4(g1, d1, wc); FMA4(g1, c1, wd);
        }

        // ---- z = tanh(f) * sigmoid(g) ----
        float z0[4], z1[4];
        #pragma unroll
        for (int j = 0; j < 4; ++j) {
            z0[j] = tanhf(f0[j]) * (1.f / (1.f + __expf(-g0[j])));
            z1[j] = tanhf(f1[j]) * (1.f / (1.f + __expf(-g1[j])));
        }
        *(float4*)(zs + s0*CURP + t0) = make_float4(z0[0],z0[1],z0[2],z0[3]);
        *(float4*)(zs + s1*CURP + t0) = make_float4(z1[0],z1[1],z1[2],z1[3]);
        __syncthreads();

        // ---- res + skip GEMMs ----
        float r0[4], r1[4];
        #pragma unroll
        for (int j = 0; j < 4; ++j) { r0[j] = bia[128+t0+j]; r1[j] = r0[j]; }
        #pragma unroll 8
        for (int k = 0; k < 64; ++k) {
            float zk0 = zs[s0*CURP+k], zk1 = zs[s1*CURP+k];
            float4 wv = *(const float4*)(wrs + k*64 + t0);
            FMA4(r0, zk0, wv); FMA4(r1, zk1, wv);
            const float* wsk = wst + k*96 + ts;
            #pragma unroll
            for (int j = 0; j < 6; ++j) {
                float w = wsk[j];
                ssum0[j] += zk0*w; ssum1[j] += zk1*w;
            }
        }
        #pragma unroll
        for (int j = 0; j < 6; ++j) {
            ssum0[j] += bia[192+ts+j];
            ssum1[j] += bia[192+ts+j];
        }

        // ---- residual update of current (owner-exclusive) ----
        {
            float4 c4 = *(float4*)(cur + s0*CURP + t0);
            c4.x += 0.3f*r0[0]; c4.y += 0.3f*r0[1];
            c4.z += 0.3f*r0[2]; c4.w += 0.3f*r0[3];
            *(float4*)(cur + s0*CURP + t0) = c4;
            float4 d4 = *(float4*)(cur + s1*CURP + t0);
            d4.x += 0.3f*r1[0]; d4.y += 0.3f*r1[1];
            d4.z += 0.3f*r1[2]; d4.w += 0.3f*r1[3];
            *(float4*)(cur + s1*CURP + t0) = d4;
        }
    }

    // ---- head ----
    __syncthreads();
    #pragma unroll
    for (int j = 0; j < 6; ++j) {
        ssm[s0*SSP + ts + j] = fmaxf(ssum0[j], 0.f);
        ssm[s1*SSP + ts + j] = fmaxf(ssum1[j], 0.f);
    }
    float* h1T = w0;
    for (int idx = tid; idx < NSKIP*NSKIP; idx += 128) {
        int k = idx / 96, t = idx - k*96;
        h1T[idx] = h1w[t*96 + k];
    }
    __syncthreads();
    {
        float a0[6], a1[6];
        #pragma unroll
        for (int j = 0; j < 6; ++j) { a0[j] = h1b[ts+j]; a1[j] = a0[j]; }
        #pragma unroll 4
        for (int k = 0; k < 96; ++k) {
            float u0 = ssm[s0*SSP+k], u1 = ssm[s1*SSP+k];
            const float* wk = h1T + k*96 + ts;
            #pragma unroll
            for (int j = 0; j < 6; ++j) {
                float w = wk[j];
                a0[j] += u0*w; a1[j] += u1*w;
            }
        }
        #pragma unroll
        for (int j = 0; j < 6; ++j) {
            hsm[s0*SSP + ts + j] = fmaxf(a0[j], 0.f);
            hsm[s1*SSP + ts + j] = fmaxf(a1[j], 0.f);
        }
    }
    __syncthreads();
    if (tid < 32) {
        int s = tid >> 1, jj = tid & 1;
        float a = h2b[jj];
        #pragma unroll 4
        for (int k = 0; k < 96; ++k)
            a += hsm[s*SSP+k] * h2w[jj*96+k];
        out[(bbase+s)*2 + jj] = a;
    }
}

// ---------------------------------------------------------------------------
// Shift: dst[n] = src[n+1], fully coalesced (lane-interleaved float4).
// Warp owns 2048 contiguous floats: A[r] = f4[r*32 + lane], r = 0..15.
// Grid 8184 x 256 covers NBUF exactly (8184*16384 = 134086656).
// ---------------------------------------------------------------------------
__global__ __launch_bounds__(256) void wn_shift(const float* __restrict__ src,
                                                float* __restrict__ dst)
{
    const int warp = threadIdx.x >> 5;
    const unsigned lane = threadIdx.x & 31;
    const size_t base = (size_t)blockIdx.x*16384 + (size_t)warp*2048;  // floats
    const float4* s4 = (const float4*)(src + base);
    float4*       d4 = (float4*)(dst + base);

    float bnd = 0.f;
    if (lane == 31) {
        size_t g = base + 2048;
        bnd = src[g < NBUF ? g : NBUF - 1];   // clamp slot is an insertion col
    }
    float4 A[16];
    #pragma unroll
    for (int r = 0; r < 16; ++r) A[r] = s4[r*32 + lane];

    #pragma unroll
    for (int r = 0; r < 16; ++r) {
        float nd = __shfl_down_sync(0xffffffffu, A[r].x, 1);
        float n0 = (r < 15) ? __shfl_sync(0xffffffffu, A[r+1].x, 0) : bnd;
        float nxt = (lane == 31) ? n0 : nd;
        d4[r*32 + lane] = make_float4(A[r].y, A[r].z, A[r].w, nxt);
    }
}

// ---------------------------------------------------------------------------
// Scatter: overwrite the 10 insertion columns j = 2^(i+1)-2 with current_i.
// ---------------------------------------------------------------------------
__global__ __launch_bounds__(256) void wn_scatter(float* __restrict__ dst)
{
    int idx = blockIdx.x*blockDim.x + threadIdx.x;
    if (idx < NBLK*NBATCH*NCH) {
        int i = idx >> 17;                 // / (2048*64)
        int r = idx & ((1 << 17) - 1);     // b*64+c
        int j = (2 << i) - 2;              // 2^(i+1)-2
        dst[(size_t)r*NCOLS + j] = g_currents[idx];
    }
}

extern "C" void kernel_launch(void* const* d_in, const int* in_sizes, int n_in,
                              void* d_out, int out_size)
{
    const float* x     = (const float*)d_in[0];
    const float* buf   = (const float*)d_in[1];
    const float* inp_w = (const float*)d_in[2];
    const float* inp_b = (const float*)d_in[3];
    const float* fw0   = (const float*)d_in[4];
    const float* fw1   = (const float*)d_in[5];
    const float* fb    = (const float*)d_in[6];
    const float* gw0   = (const float*)d_in[7];
    const float* gw1   = (const float*)d_in[8];
    const float* gb    = (const float*)d_in[9];
    const float* rw    = (const float*)d_in[10];
    const float* rb    = (const float*)d_in[11];
    const float* sw    = (const float*)d_in[12];
    const float* sb    = (const float*)d_in[13];
    const float* h1w   = (const float*)d_in[14];
    const float* h1b   = (const float*)d_in[15];
    const float* h2w   = (const float*)d_in[16];
    const float* h2b   = (const float*)d_in[17];

    float* out  = (float*)d_out;            // (2048, 2)
    float* nbuf = out + NBATCH*2;           // (2048, 64, 1023)

    // lazy one-time creation (correctness call happens before capture;
    // no device-memory delta during the captured call)
    static cudaStream_t s2 = nullptr;
    static cudaEvent_t ev_fork = nullptr, ev_join = nullptr;
    if (!s2) {
        cudaStreamCreateWithFlags(&s2, cudaStreamNonBlocking);
        cudaEventCreateWithFlags(&ev_fork, cudaEventDisableTiming);
        cudaEventCreateWithFlags(&ev_join, cudaEventDisableTiming);
    }

    const int smem_bytes = (TILE*CURP*(NBLK+2) + 5*4096 + 6144 + 288 + 2*TILE*SSP)
                           * (int)sizeof(float);
    cudaFuncSetAttribute(wn_compute, cudaFuncAttributeMaxDynamicSharedMemorySize,
                         smem_bytes);

    // fork: shift runs on s2 concurrently with compute on the main stream
    cudaEventRecord(ev_fork, 0);
    cudaStreamWaitEvent(s2, ev_fork, 0);

    wn_shift<<<8184, 256, 0, s2>>>(buf, nbuf);
    cudaEventRecord(ev_join, s2);

    wn_compute<<<NBATCH/TILE, 128, smem_bytes>>>(
        x, buf, inp_w, inp_b, fw0, fw1, fb, gw0, gw1, gb,
        rw, rb, sw, sb, h1w, h1b, h2w, h2b, out);

    // join: scatter needs both compute (g_currents) and shift (nbuf)
    cudaStreamWaitEvent(0, ev_join, 0);
    wn_scatter<<<(NBLK*NBATCH*NCH)/256, 256>>>(nbuf);
}

// round 7
// speedup vs baseline: 2.8083x; 1.2898x over previous
#include <cuda_runtime.h>

#define NBLK   10
#define NBATCH 2048
#define NCH    64
#define NSKIP  96
#define TILE   16
#define NCOLS  1023
#define CURP   68                      /* padded row stride for cur/del/z */
#define SSP    100                     /* padded row stride for skip/h */
#define NBUF   ((size_t)NBATCH*NCH*NCOLS)   /* 134086656 */

__device__ float g_currents[NBLK * NBATCH * NCH];

#define FMA4(acc, s, v) do { (acc)[0] += (s)*(v).x; (acc)[1] += (s)*(v).y; \
                             (acc)[2] += (s)*(v).z; (acc)[3] += (s)*(v).w; } while(0)

// ---------------------------------------------------------------------------
// Compute kernel: 128 CTAs x 128 threads (proven 140us layout, unchanged).
// Thread = (sp 0..7, tg 0..15): 2 samples x 4 channels register tile.
// ---------------------------------------------------------------------------
__global__ __launch_bounds__(128, 1) void wn_compute(
    const float* __restrict__ x,   const float* __restrict__ buf,
    const float* __restrict__ inp_w, const float* __restrict__ inp_b,
    const float* __restrict__ fw0, const float* __restrict__ fw1, const float* __restrict__ fb,
    const float* __restrict__ gw0, const float* __restrict__ gw1, const float* __restrict__ gb,
    const float* __restrict__ rw,  const float* __restrict__ rb,
    const float* __restrict__ sw,  const float* __restrict__ sb,
    const float* __restrict__ h1w, const float* __restrict__ h1b,
    const float* __restrict__ h2w, const float* __restrict__ h2b,
    float* __restrict__ out)
{
    extern __shared__ float sm[];
    float* cur = sm;                          // 16*68
    float* del = cur + TILE*CURP;             // 10*16*68
    float* zs  = del + NBLK*TILE*CURP;        // 16*68
    float* w0  = zs  + TILE*CURP;             // 4096  (transposed [k][t], row 64)
    float* w1  = w0 + 4096;
    float* w2  = w1 + 4096;
    float* w3  = w2 + 4096;
    float* wrs = w3 + 4096;                   // res weights
    float* wst = wrs + 4096;                  // 64*96 skip weights transposed
    float* bia = wst + 6144;                  // fb[64] gb[64] rb[64] sb[96]
    float* ssm = bia + 288;                   // 16*100 skip sums
    float* hsm = ssm + TILE*SSP;              // 16*100 hidden

    const int tid  = threadIdx.x;
    const int lane = tid & 31, warp = tid >> 5;
    const int sp = tid >> 4, tg = tid & 15;
    const int s0 = sp*2, s1 = s0+1, t0 = tg*4;
    const int bbase = blockIdx.x * TILE;

    // ---- x tile into zs scratch (16 x 32) ----
    for (int idx = tid; idx < TILE*32; idx += 128) {
        int s = idx >> 5, k = idx & 31;
        zs[idx] = x[(bbase+s)*32 + k];
    }
    __syncthreads();

    // ---- input projection: cur = x @ inp_w.T + inp_b ----
    {
        float a0[4], a1[4];
        #pragma unroll
        for (int j = 0; j < 4; ++j) { a0[j] = inp_b[t0+j]; a1[j] = a0[j]; }
        #pragma unroll 8
        for (int k = 0; k < 32; ++k) {
            float x0 = zs[s0*32+k], x1 = zs[s1*32+k];
            #pragma unroll
            for (int j = 0; j < 4; ++j) {
                float w = inp_w[(t0+j)*32 + k];
                a0[j] += x0*w; a1[j] += x1*w;
            }
        }
        #pragma unroll
        for (int j = 0; j < 4; ++j) {
            cur[s0*CURP + t0 + j] = a0[j];
            cur[s1*CURP + t0 + j] = a1[j];
        }
    }

    // ---- preload all delayed taps: del[i][s][c] = buf[b, c, 2^i - 1] ----
    for (int idx = tid; idx < NBLK*TILE*NCH; idx += 128) {
        int i = idx >> 10;
        int r = idx & 1023;
        int s = r >> 6, c = r & 63;
        int off = (1 << i) - 1;
        del[(i*TILE + s)*CURP + c] =
            buf[((size_t)(bbase+s)*NCH + c)*NCOLS + off];
    }

    float ssum0[6], ssum1[6];
    #pragma unroll
    for (int j = 0; j < 6; ++j) { ssum0[j] = 0.f; ssum1[j] = 0.f; }
    const int ts = tg*6;

    for (int i = 0; i < NBLK; ++i) {
        __syncthreads();

        // snapshot current entering block i -> g_currents[i]
        {
            float4* dst = (float4*)(g_currents + (size_t)i*NBATCH*NCH + (size_t)bbase*NCH);
            for (int idx = tid; idx < TILE*NCH/4; idx += 128) {
                int s = idx >> 4, q = idx & 15;
                dst[idx] = *(const float4*)(cur + s*CURP + q*4);
            }
        }

        // ---- stage transposed weights for this block ----
        {
            const float* srcs[5] = { fw0 + i*4096, fw1 + i*4096, gw0 + i*4096,
                                     gw1 + i*4096, rw + i*4096 };
            float* dsts[5] = { w0, w1, w2, w3, wrs };
            #pragma unroll
            for (int mm = 0; mm < 5; ++mm) {
                const float* s = srcs[mm]; float* d = dsts[mm];
                #pragma unroll
                for (int th = 0; th < 2; ++th) {
                    int t = th*32 + lane;
                    #pragma unroll
                    for (int kc = 0; kc < 4; ++kc) {
                        int k0 = warp*16 + kc*4;
                        float4 v = *(const float4*)(s + t*64 + k0);
                        d[(k0+0)*64+t] = v.x; d[(k0+1)*64+t] = v.y;
                        d[(k0+2)*64+t] = v.z; d[(k0+3)*64+t] = v.w;
                    }
                }
            }
            const float* s = sw + i*NSKIP*NCH;   // [96][64] -> wst[64][96]
            #pragma unroll
            for (int th = 0; th < 3; ++th) {
                int t = th*32 + lane;
                #pragma unroll
                for (int kc = 0; kc < 4; ++kc) {
                    int k0 = warp*16 + kc*4;
                    float4 v = *(const float4*)(s + t*64 + k0);
                    wst[(k0+0)*96+t] = v.x; wst[(k0+1)*96+t] = v.y;
                    wst[(k0+2)*96+t] = v.z; wst[(k0+3)*96+t] = v.w;
                }
            }
            if (tid < 64) {
                bia[tid]      = fb[i*64+tid];
                bia[64+tid]   = gb[i*64+tid];
                bia[128+tid]  = rb[i*64+tid];
            }
            if (tid < 96) bia[192+tid] = sb[i*NSKIP+tid];
        }
        __syncthreads();

        // ---- f/g GEMMs ----
        float f0[4], f1[4], g0[4], g1[4];
        #pragma unroll
        for (int j = 0; j < 4; ++j) {
            f0[j] = bia[t0+j];    f1[j] = f0[j];
            g0[j] = bia[64+t0+j]; g1[j] = g0[j];
        }
        const float* dle = del + i*TILE*CURP;
        #pragma unroll 8
        for (int k = 0; k < 64; ++k) {
            float d0 = dle[s0*CURP+k], d1 = dle[s1*CURP+k];
            float c0 = cur[s0*CURP+k], c1 = cur[s1*CURP+k];
            float4 wa = *(const float4*)(w0 + k*64 + t0);
            float4 wb = *(const float4*)(w1 + k*64 + t0);
            float4 wc = *(const float4*)(w2 + k*64 + t0);
            float4 wd = *(const float4*)(w3 + k*64 + t0);
            FMA4(f0, d0, wa); FMA4(f0, c0, wb);
            FMA4(f1, d1, wa); FMA4(f1, c1, wb);
            FMA4(g0, d0, wc); FMA4(g0, c0, wd);
            FMA4(g1, d1, wc); FMA4(g1, c1, wd);
        }

        // ---- z = tanh(f) * sigmoid(g) ----
        float z0[4], z1[4];
        #pragma unroll
        for (int j = 0; j < 4; ++j) {
            z0[j] = tanhf(f0[j]) * (1.f / (1.f + __expf(-g0[j])));
            z1[j] = tanhf(f1[j]) * (1.f / (1.f + __expf(-g1[j])));
        }
        *(float4*)(zs + s0*CURP + t0) = make_float4(z0[0],z0[1],z0[2],z0[3]);
        *(float4*)(zs + s1*CURP + t0) = make_float4(z1[0],z1[1],z1[2],z1[3]);
        __syncthreads();

        // ---- res + skip GEMMs ----
        float r0[4], r1[4];
        #pragma unroll
        for (int j = 0; j < 4; ++j) { r0[j] = bia[128+t0+j]; r1[j] = r0[j]; }
        #pragma unroll 8
        for (int k = 0; k < 64; ++k) {
            float zk0 = zs[s0*CURP+k], zk1 = zs[s1*CURP+k];
            float4 wv = *(const float4*)(wrs + k*64 + t0);
            FMA4(r0, zk0, wv); FMA4(r1, zk1, wv);
            const float* wsk = wst + k*96 + ts;
            #pragma unroll
            for (int j = 0; j < 6; ++j) {
                float w = wsk[j];
                ssum0[j] += zk0*w; ssum1[j] += zk1*w;
            }
        }
        #pragma unroll
        for (int j = 0; j < 6; ++j) {
            ssum0[j] += bia[192+ts+j];
            ssum1[j] += bia[192+ts+j];
        }

        // ---- residual update of current (owner-exclusive) ----
        {
            float4 c4 = *(float4*)(cur + s0*CURP + t0);
            c4.x += 0.3f*r0[0]; c4.y += 0.3f*r0[1];
            c4.z += 0.3f*r0[2]; c4.w += 0.3f*r0[3];
            *(float4*)(cur + s0*CURP + t0) = c4;
            float4 d4 = *(float4*)(cur + s1*CURP + t0);
            d4.x += 0.3f*r1[0]; d4.y += 0.3f*r1[1];
            d4.z += 0.3f*r1[2]; d4.w += 0.3f*r1[3];
            *(float4*)(cur + s1*CURP + t0) = d4;
        }
    }

    // ---- head ----
    __syncthreads();
    #pragma unroll
    for (int j = 0; j < 6; ++j) {
        ssm[s0*SSP + ts + j] = fmaxf(ssum0[j], 0.f);
        ssm[s1*SSP + ts + j] = fmaxf(ssum1[j], 0.f);
    }
    float* h1T = w0;
    for (int idx = tid; idx < NSKIP*NSKIP; idx += 128) {
        int k = idx / 96, t = idx - k*96;
        h1T[idx] = h1w[t*96 + k];
    }
    __syncthreads();
    {
        float a0[6], a1[6];
        #pragma unroll
        for (int j = 0; j < 6; ++j) { a0[j] = h1b[ts+j]; a1[j] = a0[j]; }
        #pragma unroll 4
        for (int k = 0; k < 96; ++k) {
            float u0 = ssm[s0*SSP+k], u1 = ssm[s1*SSP+k];
            const float* wk = h1T + k*96 + ts;
            #pragma unroll
            for (int j = 0; j < 6; ++j) {
                float w = wk[j];
                a0[j] += u0*w; a1[j] += u1*w;
            }
        }
        #pragma unroll
        for (int j = 0; j < 6; ++j) {
            hsm[s0*SSP + ts + j] = fmaxf(a0[j], 0.f);
            hsm[s1*SSP + ts + j] = fmaxf(a1[j], 0.f);
        }
    }
    __syncthreads();
    if (tid < 32) {
        int s = tid >> 1, jj = tid & 1;
        float a = h2b[jj];
        #pragma unroll 4
        for (int k = 0; k < 96; ++k)
            a += hsm[s*SSP+k] * h2w[jj*96+k];
        out[(bbase+s)*2 + jj] = a;
    }
}

// ---------------------------------------------------------------------------
// Shift: dst[n] = src[n+1], fully coalesced (lane-interleaved float4).
// Warp owns 2048 contiguous floats: A[r] = f4[r*32 + lane], r = 0..15.
// 128-thread CTAs (fine-grained packing next to compute CTAs).
// Grid 16368 x 128 covers NBUF exactly (16368*8192 = 134086656).
// ---------------------------------------------------------------------------
__global__ __launch_bounds__(128) void wn_shift(const float* __restrict__ src,
                                                float* __restrict__ dst)
{
    const int warp = threadIdx.x >> 5;
    const unsigned lane = threadIdx.x & 31;
    const size_t base = (size_t)blockIdx.x*8192 + (size_t)warp*2048;  // floats
    const float4* s4 = (const float4*)(src + base);
    float4*       d4 = (float4*)(dst + base);

    float bnd = 0.f;
    if (lane == 31) {
        size_t g = base + 2048;
        bnd = src[g < NBUF ? g : NBUF - 1];   // clamp slot is an insertion col
    }
    float4 A[16];
    #pragma unroll
    for (int r = 0; r < 16; ++r) A[r] = s4[r*32 + lane];

    #pragma unroll
    for (int r = 0; r < 16; ++r) {
        float nd = __shfl_down_sync(0xffffffffu, A[r].x, 1);
        float n0 = (r < 15) ? __shfl_sync(0xffffffffu, A[r+1].x, 0) : bnd;
        float nxt = (lane == 31) ? n0 : nd;
        d4[r*32 + lane] = make_float4(A[r].y, A[r].z, A[r].w, nxt);
    }
}

// ---------------------------------------------------------------------------
// Scatter: overwrite the 10 insertion columns j = 2^(i+1)-2 with current_i.
// ---------------------------------------------------------------------------
__global__ __launch_bounds__(256) void wn_scatter(float* __restrict__ dst)
{
    int idx = blockIdx.x*blockDim.x + threadIdx.x;
    if (idx < NBLK*NBATCH*NCH) {
        int i = idx >> 17;                 // / (2048*64)
        int r = idx & ((1 << 17) - 1);     // b*64+c
        int j = (2 << i) - 2;              // 2^(i+1)-2
        dst[(size_t)r*NCOLS + j] = g_currents[idx];
    }
}

extern "C" void kernel_launch(void* const* d_in, const int* in_sizes, int n_in,
                              void* d_out, int out_size)
{
    const float* x     = (const float*)d_in[0];
    const float* buf   = (const float*)d_in[1];
    const float* inp_w = (const float*)d_in[2];
    const float* inp_b = (const float*)d_in[3];
    const float* fw0   = (const float*)d_in[4];
    const float* fw1   = (const float*)d_in[5];
    const float* fb    = (const float*)d_in[6];
    const float* gw0   = (const float*)d_in[7];
    const float* gw1   = (const float*)d_in[8];
    const float* gb    = (const float*)d_in[9];
    const float* rw    = (const float*)d_in[10];
    const float* rb    = (const float*)d_in[11];
    const float* sw    = (const float*)d_in[12];
    const float* sb    = (const float*)d_in[13];
    const float* h1w   = (const float*)d_in[14];
    const float* h1b   = (const float*)d_in[15];
    const float* h2w   = (const float*)d_in[16];
    const float* h2b   = (const float*)d_in[17];

    float* out  = (float*)d_out;            // (2048, 2)
    float* nbuf = out + NBATCH*2;           // (2048, 64, 1023)

    // lazy one-time creation (first call = correctness run, before capture)
    static cudaStream_t s2 = nullptr;
    static cudaEvent_t ev_fork = nullptr, ev_join = nullptr;
    if (!s2) {
        int lo, hi;
        cudaDeviceGetStreamPriorityRange(&lo, &hi);   // lo = LEAST priority
        cudaStreamCreateWithPriority(&s2, cudaStreamNonBlocking, lo);
        cudaEventCreateWithFlags(&ev_fork, cudaEventDisableTiming);
        cudaEventCreateWithFlags(&ev_join, cudaEventDisableTiming);
    }

    const int smem_bytes = (TILE*CURP*(NBLK+2) + 5*4096 + 6144 + 288 + 2*TILE*SSP)
                           * (int)sizeof(float);
    cudaFuncSetAttribute(wn_compute, cudaFuncAttributeMaxDynamicSharedMemorySize,
                         smem_bytes);

    // fork: compute launched FIRST (grabs its SM slots); shift fills the rest
    cudaEventRecord(ev_fork, 0);
    cudaStreamWaitEvent(s2, ev_fork, 0);

    wn_compute<<<NBATCH/TILE, 128, smem_bytes>>>(
        x, buf, inp_w, inp_b, fw0, fw1, fb, gw0, gw1, gb,
        rw, rb, sw, sb, h1w, h1b, h2w, h2b, out);

    wn_shift<<<16368, 128, 0, s2>>>(buf, nbuf);
    cudaEventRecord(ev_join, s2);

    // join: scatter needs both compute (g_currents) and shift (nbuf)
    cudaStreamWaitEvent(0, ev_join, 0);
    wn_scatter<<<(NBLK*NBATCH*NCH)/256, 256>>>(nbuf);
}